// round 12
// baseline (speedup 1.0000x reference)
#include <cuda_runtime.h>
#include <cstdint>

// ---------------- problem constants ----------------
#define BJ   128          // batch
#define JJ   22           // joints
#define EE   8            // experts
#define PAIRS (JJ*EE)     // 176
#define DT_  9
#define DD   64
#define D_IN  2304        // DT*K*D
#define D_OUT 576         // DT*D
#define H1_  256
#define H2_  128

// ---------------- scratch (static device memory; no allocations) ----------------
#define OFF_INP  0
#define OFF_H1   6488064
#define OFF_H2   12255232
#define OFF_MU   15138816
#define OFF_LV   18022400
#define OFF_G    20905984
#define OFF_XHAT 26673152
#define SCRATCH_TOTAL 39649280

__device__ __align__(16) float g_scratch[SCRATCH_TOTAL];
__device__ float g_err[PAIRS * BJ];

// TF32 rounding (cvt.rna — the HW conversion cublas/cutlass use on tensor-core input paths)
__device__ __forceinline__ float tf32r(float f) {
    uint32_t u;
    asm("cvt.rna.tf32.f32 %0, %1;" : "=r"(u) : "f"(f));
    return __uint_as_float(u);
}

// ---------------- gather: inp[j][b][t*256+k*64+d] = x[b][t][nbr[j][k]][d] ----------------
__global__ void gather_kernel(const float* __restrict__ x,
                              const int* __restrict__ nbr,
                              float* __restrict__ inp)
{
    int idx = blockIdx.x * blockDim.x + threadIdx.x;
    if (idx >= JJ * BJ * D_IN) return;
    int j = idx / (BJ * D_IN);
    int r = idx - j * (BJ * D_IN);
    int b = r / D_IN;
    int c = r - b * D_IN;
    int t = c >> 8;          // / 256
    int k = (c >> 6) & 3;
    int d = c & 63;
    int n = nbr[j * 4 + k];
    inp[idx] = x[(((size_t)b * DT_ + t) * JJ + n) * DD + d];
}

// ---------------- batched GEMM, TF32-emulated inputs, fp32 accumulate ----------------
// C[p] = act(tf32(A[p/a_div]) @ tf32(W[p]) + bias[p])  — matches JAX/GPU default
// matmul precision (TF32 on tensor-core fp32 paths). Accumulation order differences
// vs cublas are ~1e-11 in err units — irrelevant; only TF32 input rounding matters.
template<bool RELU>
__global__ void __launch_bounds__(256, 2) gemm_bias(
    const float* __restrict__ A, const float* __restrict__ W,
    const float* __restrict__ bias, float* __restrict__ C,
    int K, int N, int a_div)
{
    constexpr int BM = 128, BN = 128, BK = 16;
    const int pair = blockIdx.y;
    const int n0 = blockIdx.x * BN;
    const int tid = threadIdx.x;

    const float* Ap = A + (size_t)(pair / a_div) * (size_t)BM * K;
    const float* Wp = W + (size_t)pair * (size_t)K * N;
    const float* bp = bias + (size_t)pair * N;
    float* Cp = C + (size_t)pair * (size_t)BM * N;

    __shared__ float As[BK][BM];
    __shared__ float Bs[BK][BN];

    const int a_row = tid >> 1;          // 0..127
    const int a_k   = (tid & 1) * 8;     // 0 or 8
    const int b_row = tid >> 4;          // 0..15
    const int b_c4  = tid & 15;          // 0..15

    const int rm0 = (tid >> 4) * 8;      // 0..120
    const int rn0 = (tid & 15) * 8;      // 0..120

    float acc[8][8];
    #pragma unroll
    for (int i = 0; i < 8; i++)
        #pragma unroll
        for (int j = 0; j < 8; j++) acc[i][j] = 0.f;

    for (int kk = 0; kk < K; kk += BK) {
        // load A tile (transposed into As[k][m]), rounded to TF32
        #pragma unroll
        for (int v = 0; v < 2; v++) {
            float4 a = *reinterpret_cast<const float4*>(
                Ap + (size_t)a_row * K + kk + a_k + v * 4);
            As[a_k + v * 4 + 0][a_row] = tf32r(a.x);
            As[a_k + v * 4 + 1][a_row] = tf32r(a.y);
            As[a_k + v * 4 + 2][a_row] = tf32r(a.z);
            As[a_k + v * 4 + 3][a_row] = tf32r(a.w);
        }
        // load B tile (N-guarded; N is always a multiple of 4), rounded to TF32
        #pragma unroll
        for (int v = 0; v < 2; v++) {
            int col = b_c4 * 4 + v * 64;
            float4 b = make_float4(0.f, 0.f, 0.f, 0.f);
            if (n0 + col < N)
                b = *reinterpret_cast<const float4*>(
                    Wp + (size_t)(kk + b_row) * N + n0 + col);
            Bs[b_row][col + 0] = tf32r(b.x);
            Bs[b_row][col + 1] = tf32r(b.y);
            Bs[b_row][col + 2] = tf32r(b.z);
            Bs[b_row][col + 3] = tf32r(b.w);
        }
        __syncthreads();

        #pragma unroll
        for (int k = 0; k < BK; k++) {
            float ra[8], rb[8];
            #pragma unroll
            for (int i = 0; i < 2; i++) {
                float4 t4 = *reinterpret_cast<const float4*>(&As[k][rm0 + i * 4]);
                ra[i*4+0] = t4.x; ra[i*4+1] = t4.y; ra[i*4+2] = t4.z; ra[i*4+3] = t4.w;
            }
            #pragma unroll
            for (int i = 0; i < 2; i++) {
                float4 t4 = *reinterpret_cast<const float4*>(&Bs[k][rn0 + i * 4]);
                rb[i*4+0] = t4.x; rb[i*4+1] = t4.y; rb[i*4+2] = t4.z; rb[i*4+3] = t4.w;
            }
            #pragma unroll
            for (int i = 0; i < 8; i++)
                #pragma unroll
                for (int j = 0; j < 8; j++)
                    acc[i][j] = fmaf(ra[i], rb[j], acc[i][j]);
        }
        __syncthreads();
    }

    #pragma unroll
    for (int j = 0; j < 8; j++) {
        int n = n0 + rn0 + j;
        if (n < N) {
            float bv = bp[n];
            #pragma unroll
            for (int i = 0; i < 8; i++) {
                float v = acc[i][j] + bv;
                if (RELU) v = fmaxf(v, 0.f);
                Cp[(size_t)(rm0 + i) * N + n] = v;
            }
        }
    }
}

// ---------------- err[p][b]: XLA:GPU row-reduction emitter order ----------------
// One warp per 576-elem row, vectorized x2: thread t accumulates element pairs
// (2t + 64k, 2t + 64k + 1), k = 0..8, sequentially into one scalar accumulator
// (FMA contraction, as NVPTX emits). Then 5-level warp shuffle-down tree; lane 0
// applies the mean via a true correctly-rounded fdiv by 576 (XLA does not turn
// non-power-of-2 divides into reciprocal multiplies).
__global__ void err_kernel(const float* __restrict__ xhat,
                           const float* __restrict__ x,
                           float* __restrict__ err)
{
    int w = (blockIdx.x * blockDim.x + threadIdx.x) >> 5;
    int lane = threadIdx.x & 31;
    if (w >= PAIRS * BJ) return;
    int p = w / BJ;
    int b = w - p * BJ;
    int j = p / EE;
    const float* xh = xhat + ((size_t)p * BJ + b) * D_OUT;
    const float* xb = x + (size_t)b * DT_ * JJ * DD + (size_t)j * DD;

    float acc = 0.f;
    #pragma unroll
    for (int k = 0; k < 9; k++) {
        int i0 = 2 * lane + 64 * k;
        int t0 = i0 >> 6, d0i = i0 & 63;
        int i1 = i0 + 1;
        int t1 = i1 >> 6, d1i = i1 & 63;
        float tg0 = __ldg(xb + (size_t)t0 * JJ * DD + d0i);
        float tg1 = __ldg(xb + (size_t)t1 * JJ * DD + d1i);
        float d0 = __fsub_rn(__ldg(xh + i0), tg0);
        float d1 = __fsub_rn(__ldg(xh + i1), tg1);
        acc = fmaf(d0, d0, acc);   // vec element 0 first
        acc = fmaf(d1, d1, acc);   // then vec element 1
    }
    // warp shuffle-down tree
    #pragma unroll
    for (int o = 16; o > 0; o >>= 1)
        acc = __fadd_rn(acc, __shfl_down_sync(0xffffffffu, acc, o));
    if (lane == 0) err[(size_t)p * BJ + b] = __fdiv_rn(acc, 576.0f);
}

// ---------------- select: argmin over e (strict <, ties -> lowest index) ----------------
// out layout (float32): mu(B,J,128) | lv(B,J,128) | xhat(B,DT,J,D) | idx(B,J)
#define OUT_MU   0
#define OUT_LV   360448
#define OUT_XH   720896
#define OUT_IDX  2342912
__global__ void select_kernel(const float* __restrict__ mu,
                              const float* __restrict__ lv,
                              const float* __restrict__ xhat,
                              const float* __restrict__ err,
                              float* __restrict__ out)
{
    int j = blockIdx.x;
    int b = blockIdx.y;
    int tid = threadIdx.x;  // 128

    float best = err[(size_t)(j * EE + 0) * BJ + b];
    int bi = 0;
    #pragma unroll
    for (int e = 1; e < EE; e++) {
        float v = err[(size_t)(j * EE + e) * BJ + b];
        if (v < best) { best = v; bi = e; }   // strict <: lowest index wins ties
    }
    int p = j * EE + bi;

    size_t base = ((size_t)b * JJ + j) * H2_;
    out[OUT_MU + base + tid] = mu[((size_t)p * BJ + b) * H2_ + tid];
    out[OUT_LV + base + tid] = lv[((size_t)p * BJ + b) * H2_ + tid];

    const float* xh = xhat + ((size_t)p * BJ + b) * D_OUT;
    for (int i = tid; i < D_OUT; i += 128) {
        int t = i >> 6, d = i & 63;
        out[OUT_XH + (((size_t)b * DT_ + t) * JJ + j) * DD + d] = xh[i];
    }
    if (tid == 0) out[OUT_IDX + (size_t)b * JJ + j] = (float)bi;
}

// ---------------- launch ----------------
extern "C" void kernel_launch(void* const* d_in, const int* in_sizes, int n_in,
                              void* d_out, int out_size)
{
    const float* x         = (const float*)d_in[0];
    const int*   neighbors = (const int*)d_in[1];
    const float* W_e1 = (const float*)d_in[2];
    const float* b_e1 = (const float*)d_in[3];
    const float* W_e2 = (const float*)d_in[4];
    const float* b_e2 = (const float*)d_in[5];
    const float* W_mu = (const float*)d_in[6];
    const float* b_mu = (const float*)d_in[7];
    const float* W_lv = (const float*)d_in[8];
    const float* b_lv = (const float*)d_in[9];
    const float* W_d1 = (const float*)d_in[10];
    const float* b_d1 = (const float*)d_in[11];
    const float* W_d2 = (const float*)d_in[12];
    const float* b_d2 = (const float*)d_in[13];
    float* out = (float*)d_out;

    float* scratch = nullptr;
    cudaGetSymbolAddress((void**)&scratch, g_scratch);
    float* errbuf = nullptr;
    cudaGetSymbolAddress((void**)&errbuf, g_err);

    float* s_inp  = scratch + OFF_INP;
    float* s_h1   = scratch + OFF_H1;
    float* s_h2   = scratch + OFF_H2;
    float* s_mu   = scratch + OFF_MU;
    float* s_lv   = scratch + OFF_LV;
    float* s_g    = scratch + OFF_G;
    float* s_xhat = scratch + OFF_XHAT;

    // 1. gather neighbor features
    {
        int total = JJ * BJ * D_IN;
        gather_kernel<<<(total + 255) / 256, 256>>>(x, neighbors, s_inp);
    }
    // 2. h1 = relu(inp @ W_e1 + b_e1)   [K=2304, N=256], A shared across e (a_div=8)
    gemm_bias<true ><<<dim3(2, PAIRS), 256>>>(s_inp, W_e1, b_e1, s_h1, D_IN, H1_, EE);
    // 3. h2 = relu(h1 @ W_e2 + b_e2)    [K=256, N=128]
    gemm_bias<true ><<<dim3(1, PAIRS), 256>>>(s_h1, W_e2, b_e2, s_h2, H1_, H2_, 1);
    // 4. mu = h2 @ W_mu + b_mu          [K=128, N=128]
    gemm_bias<false><<<dim3(1, PAIRS), 256>>>(s_h2, W_mu, b_mu, s_mu, H2_, H2_, 1);
    // 5. lv = h2 @ W_lv + b_lv
    gemm_bias<false><<<dim3(1, PAIRS), 256>>>(s_h2, W_lv, b_lv, s_lv, H2_, H2_, 1);
    // 6. g = relu(mu @ W_d1 + b_d1)     [K=128, N=256]
    gemm_bias<true ><<<dim3(2, PAIRS), 256>>>(s_mu, W_d1, b_d1, s_g, H2_, H1_, 1);
    // 7. xhat = g @ W_d2 + b_d2         [K=256, N=576]
    gemm_bias<false><<<dim3(5, PAIRS), 256>>>(s_g, W_d2, b_d2, s_xhat, H1_, D_OUT, 1);
    // 8. per-(p,b) reconstruction error: XLA:GPU vec2 warp row-reduce
    {
        int warps = PAIRS * BJ;                 // 22528
        err_kernel<<<(warps * 32 + 255) / 256, 256>>>(s_xhat, x, errbuf);
    }
    // 9. argmin (ties -> lowest index) + gather outputs
    select_kernel<<<dim3(JJ, BJ), 128>>>(s_mu, s_lv, s_xhat, errbuf, out);
}